// round 13
// baseline (speedup 1.0000x reference)
#include <cuda_runtime.h>
#include <cuda_fp16.h>
#include <cuda_bf16.h>
#include <math.h>
#include <stdint.h>

// prep-built weight images, LDG.128-friendly order:
// u32 idx = ((kb*16 + warp)*32 + lane)*8 + nbi*2 + reg   (nbi = nb within warp)
__device__ __align__(16) uint32_t gWahHi[131072];
__device__ __align__(16) uint32_t gWahLo[131072];
__device__ __align__(16) uint32_t gWaaHi[131072];
__device__ __align__(16) uint32_t gWaaLo[131072];
__device__ __align__(16) uint32_t gWbHi [16384];
__device__ __align__(16) uint32_t gWbLo [16384];

namespace {
constexpr int H = 16, C = 32, HID = 512, SKUD = 64, ROWS = 32, NTHR = 512;
constexpr float TEMP_INV = 1.0f / 0.7f, TMAX = 365.0f, LN_EPS = 1e-3f;
constexpr int XSTR = 1040;                 // X image row stride in bytes (520 bf16)
// smem byte offsets
constexpr int OFF_XHI = 0;                 // 32*1040 = 33280
constexpr int OFF_XLO = 33280;
constexpr int OFF_WO  = 66560;             // 512 f32
constexpr int OFF_PS0 = 68608;             // 16*32 f32
constexpr int OFF_PS1 = 70656;             // 16*32 f32
constexpr int OFF_GMX = 72704;             // 32 f32
constexpr int OFF_WAWO= 72832;             // 64 f32
constexpr int SMEM_BYTES = 73088;
}

using ull = unsigned long long;

__device__ __forceinline__ ull pack2(float x, float y) {
    ull r; asm("mov.b64 %0, {%1, %2};" : "=l"(r) : "f"(x), "f"(y)); return r;
}
__device__ __forceinline__ float2 unpack2(ull v) {
    float2 f; asm("mov.b64 {%0, %1}, %2;" : "=f"(f.x), "=f"(f.y) : "l"(v)); return f;
}
__device__ __forceinline__ void ffma2(ull& d, ull a, ull b) {
    asm("fma.rn.f32x2 %0, %1, %2, %0;" : "+l"(d) : "l"(a), "l"(b));
}
__device__ __forceinline__ float mishf(float x) {
    float sp = (x > 20.f) ? x : log1pf(expf(x));
    return x * tanhf(sp);
}
__device__ __forceinline__ uint32_t s2u(const void* p) {
    uint32_t a;
    asm("{ .reg .u64 t; cvta.to.shared.u64 t, %1; cvt.u32.u64 %0, t; }" : "=r"(a) : "l"(p));
    return a;
}
__device__ __forceinline__ uint32_t packbf2(float a, float b) {
    __nv_bfloat162 v = __floats2bfloat162_rn(a, b);
    return *reinterpret_cast<uint32_t*>(&v);
}
__device__ __forceinline__ float2 unbf2(uint32_t u) {
    __nv_bfloat162 v = *reinterpret_cast<__nv_bfloat162*>(&u);
    return make_float2(__bfloat162float(v.x), __bfloat162float(v.y));
}
__device__ __forceinline__ void hmma(float* acc, uint32_t a0, uint32_t a1,
                                     uint32_t a2, uint32_t a3, uint32_t b0, uint32_t b1) {
    asm volatile("mma.sync.aligned.m16n8k16.row.col.f32.bf16.bf16.f32 "
        "{%0,%1,%2,%3}, {%4,%5,%6,%7}, {%8,%9}, {%0,%1,%2,%3};"
        : "+f"(acc[0]), "+f"(acc[1]), "+f"(acc[2]), "+f"(acc[3])
        : "r"(a0), "r"(a1), "r"(a2), "r"(a3), "r"(b0), "r"(b1));
}
__device__ __forceinline__ void ldsm4(uint32_t* r, uint32_t addr) {
    asm volatile("ldmatrix.sync.aligned.m8n8.x4.shared.b16 {%0,%1,%2,%3}, [%4];"
        : "=r"(r[0]), "=r"(r[1]), "=r"(r[2]), "=r"(r[3]) : "r"(addr));
}

// split-bf16 MMA GEMM, barrier-free. Warp tile 32 rows x 32 cols.
// A frags via ldmatrix.x4 from smem X images; B frag-order from global (L2)
// via LDG.128, register double-buffered across kb.
__device__ __forceinline__ void mma_gemm(
    const uint32_t* __restrict__ gHi, const uint32_t* __restrict__ gLo,
    int nk, uint32_t xh_lane, uint32_t xl_lane,
    float acc[2][4][4], int wid, int tx)
{
#pragma unroll
    for (int mi = 0; mi < 2; mi++)
#pragma unroll
        for (int nb = 0; nb < 4; nb++)
#pragma unroll
            for (int e = 0; e < 4; e++) acc[mi][nb][e] = 0.f;

    const uint4* pH = (const uint4*)gHi;
    const uint4* pL = (const uint4*)gLo;
    const int bidx = (wid * 32 + tx) * 2;   // uint4 index; +1024 per kb

    uint4 bh[2][2], bl[2][2];
    bh[0][0] = __ldg(pH + bidx);     bh[0][1] = __ldg(pH + bidx + 1);
    bl[0][0] = __ldg(pL + bidx);     bl[0][1] = __ldg(pL + bidx + 1);
#pragma unroll 2
    for (int kb = 0; kb < nk; kb++) {
        int cur = kb & 1, nxt = cur ^ 1;
        if (kb + 1 < nk) {
            int p = bidx + (kb + 1) * 1024;
            bh[nxt][0] = __ldg(pH + p);     bh[nxt][1] = __ldg(pH + p + 1);
            bl[nxt][0] = __ldg(pL + p);     bl[nxt][1] = __ldg(pL + p + 1);
        }
        uint32_t ah[2][4], al[2][4];
#pragma unroll
        for (int mi = 0; mi < 2; mi++) {
            ldsm4(ah[mi], xh_lane + mi * 16 * XSTR + kb * 32);
            ldsm4(al[mi], xl_lane + mi * 16 * XSTR + kb * 32);
        }
        uint32_t bhr[8], blr[8];
        bhr[0] = bh[cur][0].x; bhr[1] = bh[cur][0].y; bhr[2] = bh[cur][0].z; bhr[3] = bh[cur][0].w;
        bhr[4] = bh[cur][1].x; bhr[5] = bh[cur][1].y; bhr[6] = bh[cur][1].z; bhr[7] = bh[cur][1].w;
        blr[0] = bl[cur][0].x; blr[1] = bl[cur][0].y; blr[2] = bl[cur][0].z; blr[3] = bl[cur][0].w;
        blr[4] = bl[cur][1].x; blr[5] = bl[cur][1].y; blr[6] = bl[cur][1].z; blr[7] = bl[cur][1].w;
#pragma unroll
        for (int nb = 0; nb < 4; nb++) {
#pragma unroll
            for (int mi = 0; mi < 2; mi++) {
                hmma(acc[mi][nb], ah[mi][0], ah[mi][1], ah[mi][2], ah[mi][3],
                     bhr[2 * nb], bhr[2 * nb + 1]);
                hmma(acc[mi][nb], ah[mi][0], ah[mi][1], ah[mi][2], ah[mi][3],
                     blr[2 * nb], blr[2 * nb + 1]);
                hmma(acc[mi][nb], al[mi][0], al[mi][1], al[mi][2], al[mi][3],
                     bhr[2 * nb], bhr[2 * nb + 1]);
            }
        }
    }
}

// ---------- prep: build LDG.128-order bf16 hi/lo weight images ---------------
__global__ void prep_kernel(const float* __restrict__ Wah,
                            const float* __restrict__ Waa,
                            const float* __restrict__ Wb)
{
    int gid = blockIdx.x * 256 + threadIdx.x;
    const float* W; uint32_t *dHi, *dLo; int idx;
    if (gid < 131072)      { W = Wah; dHi = gWahHi; dLo = gWahLo; idx = gid; }
    else if (gid < 262144) { W = Waa; dHi = gWaaHi; dLo = gWaaLo; idx = gid - 131072; }
    else                   { W = Wb;  dHi = gWbHi;  dLo = gWbLo;  idx = gid - 262144; }
    int reg = idx & 1, lane = (idx >> 1) & 31, nb = (idx >> 6) & 63, kb = idx >> 12;
    int tg = lane & 3, gq = lane >> 2;
    int k0 = kb * 16 + 2 * tg + reg * 8;
    int n  = nb * 8 + gq;
    float w0 = W[(size_t)k0 * 512 + n];
    float w1 = W[(size_t)(k0 + 1) * 512 + n];
    __nv_bfloat16 h0 = __float2bfloat16(w0), h1 = __float2bfloat16(w1);
    float l0f = w0 - __bfloat162float(h0), l1f = w1 - __bfloat162float(h1);
    __nv_bfloat162 hv(h0, h1);
    __nv_bfloat162 lv(__float2bfloat16(l0f), __float2bfloat16(l1f));
    int w = nb >> 2, nbi = nb & 3;
    uint32_t nidx = (uint32_t)(((kb * 16 + w) * 32 + lane) * 8 + nbi * 2 + reg);
    dHi[nidx] = *reinterpret_cast<uint32_t*>(&hv);
    dLo[nidx] = *reinterpret_cast<uint32_t*>(&lv);
}

__global__ __launch_bounds__(NTHR)
void holiday_mma_kernel(
    const float* __restrict__ inputs, const float* __restrict__ sku,
    const float* __restrict__ deltas, const float* __restrict__ ln_gamma,
    const float* __restrict__ ln_beta, const float* __restrict__ attn_w,
    const float* __restrict__ Wh, const float* __restrict__ Wa,
    const float* __restrict__ Wo, float* __restrict__ out)
{
    extern __shared__ char smc[];
    float* sWo   = (float*)(smc + OFF_WO);
    float* ps0   = (float*)(smc + OFF_PS0);
    float* ps1   = (float*)(smc + OFF_PS1);
    float* gmaxA = (float*)(smc + OFF_GMX);
    float* sWaWo = (float*)(smc + OFF_WAWO);

    const int tid = threadIdx.x, tx = tid & 31, wid = tid >> 5;   // 16 warps
    const int tg = tx & 3, gq = tx >> 2;
    const int wn0 = wid * 32;
    const int b0 = blockIdx.x * ROWS;
    const unsigned FULL = 0xffffffffu;
    const uint32_t sb = s2u(smc);
    // ldmatrix lane base address (mi=0, kb=0): matrices {rows0-7 klo, rows8-15 klo,
    // rows0-7 khi, rows8-15 khi}
    const uint32_t lrow = (tx & 7) + ((tx >> 3) & 1) * 8;
    const uint32_t lcol = (tx >> 4) * 16;
    const uint32_t xh_lane = sb + OFF_XHI + lrow * XSTR + lcol;
    const uint32_t xl_lane = sb + OFF_XLO + lrow * XSTR + lcol;

    // ---- prologue: Wo, alpha fold, changepoints ----------------------------
    for (int i = tid; i < HID; i += NTHR) sWo[i] = Wo[i];
#pragma unroll
    for (int si = 0; si < 4; si++) {
        int s = wid * 4 + si;
        float p = 0.f;
#pragma unroll
        for (int j = 0; j < 16; j++) {
            int c = tx + 32 * j;
            p = fmaf(__ldg(Wa + s * HID + c), __ldg(Wo + c), p);
        }
#pragma unroll
        for (int o = 16; o > 0; o >>= 1) p += __shfl_xor_sync(FULL, p, o);
        if (tx == 0) sWaWo[s] = p;
    }
    float cps_r;
    {
        float d  = deltas[wid * C + tx];
        float sp = (d > 20.f) ? d : log1pf(expf(d));
        float s  = sp;
#pragma unroll
        for (int o = 1; o < 32; o <<= 1) {
            float v = __shfl_up_sync(FULL, s, o);
            if (tx >= o) s += v;
        }
        cps_r = s * (TMAX / __shfl_sync(FULL, s, 31));
    }

    // ---- stage sku into X images (rows 0..31, k 0..63) ---------------------
    {
        int r = tid >> 4, k0 = (tid & 15) * 4;
        float4 a = *(const float4*)(sku + (size_t)(b0 + r) * SKUD + k0);
        float v[4] = {a.x, a.y, a.z, a.w};
#pragma unroll
        for (int e = 0; e < 2; e++) {
            float v0 = v[2 * e], v1 = v[2 * e + 1];
            __nv_bfloat16 h0 = __float2bfloat16(v0), h1 = __float2bfloat16(v1);
            uint32_t off = r * XSTR + (k0 + 2 * e) * 2;
            __nv_bfloat162 hv2(h0, h1);
            *(uint32_t*)(smc + OFF_XHI + off) = *reinterpret_cast<uint32_t*>(&hv2);
            *(uint32_t*)(smc + OFF_XLO + off) =
                packbf2(v0 - __bfloat162float(h0), v1 - __bfloat162float(h1));
        }
    }
    __syncthreads();

    float acc[2][4][4];

    // ---- GEMM0: beta = sigmoid(sku @ Wb) -> half2 regs ---------------------
    mma_gemm(gWbHi, gWbLo, 4, xh_lane, xl_lane, acc, wid, tx);
    __half2 bh2[2][4][2];
#pragma unroll
    for (int mi = 0; mi < 2; mi++)
#pragma unroll
        for (int nb = 0; nb < 4; nb++) {
            bh2[mi][nb][0] = __floats2half2_rn(
                1.f / (1.f + expf(-acc[mi][nb][0])), 1.f / (1.f + expf(-acc[mi][nb][1])));
            bh2[mi][nb][1] = __floats2half2_rn(
                1.f / (1.f + expf(-acc[mi][nb][2])), 1.f / (1.f + expf(-acc[mi][nb][3])));
        }
    __syncthreads();   // all GEMM0 A-reads done -> stage1 may overwrite X

    // ---- stage 1: features -> X images (h = wid, r = tx) -------------------
    {
        int h = wid;
        float t = inputs[(size_t)(b0 + tx) * H + h];
        float f[C], e[C];
        float mu = 0.f;
#pragma unroll
        for (int c = 0; c < C; c++) {
            float cp = __shfl_sync(FULL, cps_r, c);
            f[c] = fmaxf(t - cp, 0.f); mu += f[c];
        }
        mu *= (1.0f / C);
        float var = 0.f;
#pragma unroll
        for (int c = 0; c < C; c++) { float d = f[c] - mu; var = fmaf(d, d, var); }
        var *= (1.0f / C);
        float rs = rsqrtf(var + LN_EPS);
        float aw = __ldg(attn_w + h) * TEMP_INV;
        float m = -3.4e38f;
#pragma unroll
        for (int c = 0; c < C; c++) {
            float n = fmaf((f[c] - mu) * rs, __ldg(ln_gamma + h * C + c),
                           __ldg(ln_beta + h * C + c));
            f[c] = n;
            m = fmaxf(m, n * aw);
        }
        float s = 0.f;
#pragma unroll
        for (int c = 0; c < C; c++) { e[c] = expf(f[c] * aw - m); s += e[c]; }
        float inv = 1.0f / s;
        ull hid2[16];
#pragma unroll
        for (int d = 0; d < 16; d++) hid2[d] = 0ull;
#pragma unroll
        for (int c = 0; c < C; c++) {
            float a = f[c] * e[c] * inv;
            ull a2 = pack2(a, a);
            const ull* wr = reinterpret_cast<const ull*>(Wh + (h * C + c) * C);
#pragma unroll
            for (int d = 0; d < 16; d++) ffma2(hid2[d], a2, wr[d]);
        }
#pragma unroll
        for (int d = 0; d < 16; d++) {
            float2 hv = unpack2(hid2[d]);
            float v0 = mishf(hv.x), v1 = mishf(hv.y);
            __nv_bfloat16 h0 = __float2bfloat16(v0), h1 = __float2bfloat16(v1);
            uint32_t off = tx * XSTR + (h * 32 + 2 * d) * 2;
            __nv_bfloat162 hv2(h0, h1);
            *(uint32_t*)(smc + OFF_XHI + off) = *reinterpret_cast<uint32_t*>(&hv2);
            *(uint32_t*)(smc + OFF_XLO + off) =
                packbf2(v0 - __bfloat162float(h0), v1 - __bfloat162float(h1));
        }
    }
    __syncthreads();

    // ---- GEMM1: H1 = mish(X @ Wah) -----------------------------------------
    mma_gemm(gWahHi, gWahLo, 32, xh_lane, xl_lane, acc, wid, tx);
    __syncthreads();   // all X reads done -> overwrite with H1
#pragma unroll
    for (int mi = 0; mi < 2; mi++)
#pragma unroll
        for (int nb = 0; nb < 4; nb++)
#pragma unroll
            for (int rb = 0; rb < 2; rb++) {
                int row = mi * 16 + rb * 8 + gq;
                int n = wn0 + nb * 8 + 2 * tg;
                float v0 = mishf(acc[mi][nb][rb * 2]);
                float v1 = mishf(acc[mi][nb][rb * 2 + 1]);
                __nv_bfloat16 h0 = __float2bfloat16(v0), h1 = __float2bfloat16(v1);
                uint32_t off = row * XSTR + n * 2;
                __nv_bfloat162 hv2(h0, h1);
                *(uint32_t*)(smc + OFF_XHI + off) = *reinterpret_cast<uint32_t*>(&hv2);
                *(uint32_t*)(smc + OFF_XLO + off) =
                    packbf2(v0 - __bfloat162float(h0), v1 - __bfloat162float(h1));
            }
    __syncthreads();

    // ---- GEMM2: logits = H1 @ Waa ------------------------------------------
    mma_gemm(gWaaHi, gWaaLo, 32, xh_lane, xl_lane, acc, wid, tx);

    // ---- epilogue -----------------------------------------------------------
    float mx[4] = {-3.4e38f, -3.4e38f, -3.4e38f, -3.4e38f};
#pragma unroll
    for (int mi = 0; mi < 2; mi++)
#pragma unroll
        for (int nb = 0; nb < 4; nb++)
#pragma unroll
            for (int rb = 0; rb < 2; rb++)
                mx[mi * 2 + rb] = fmaxf(mx[mi * 2 + rb],
                    fmaxf(acc[mi][nb][rb * 2], acc[mi][nb][rb * 2 + 1]));
#pragma unroll
    for (int q = 0; q < 4; q++) {
        mx[q] = fmaxf(mx[q], __shfl_xor_sync(FULL, mx[q], 1));
        mx[q] = fmaxf(mx[q], __shfl_xor_sync(FULL, mx[q], 2));
    }
    if (tg == 0) {
#pragma unroll
        for (int q = 0; q < 4; q++)
            ps0[wid * 32 + (q >> 1) * 16 + (q & 1) * 8 + gq] = mx[q];
    }
    __syncthreads();
    if (tid < 32) {
        float m = -3.4e38f;
#pragma unroll
        for (int w = 0; w < 16; w++) m = fmaxf(m, ps0[w * 32 + tid]);
        gmaxA[tid] = m;
    }
    __syncthreads();

    float sv[4] = {0.f, 0.f, 0.f, 0.f}, dv[4] = {0.f, 0.f, 0.f, 0.f};
#pragma unroll
    for (int mi = 0; mi < 2; mi++)
#pragma unroll
        for (int rb = 0; rb < 2; rb++) {
            int row = mi * 16 + rb * 8 + gq;
            float gm = gmaxA[row];
            float s = 0.f, d = 0.f;
#pragma unroll
            for (int nb = 0; nb < 4; nb++) {
                int n = wn0 + nb * 8 + 2 * tg;
                float e0 = expf((acc[mi][nb][rb * 2]     - gm) * TEMP_INV);
                float e1 = expf((acc[mi][nb][rb * 2 + 1] - gm) * TEMP_INV);
                uint32_t off = row * XSTR + n * 2;
                float2 hh = unbf2(*(const uint32_t*)(smc + OFF_XHI + off));
                float2 hl = unbf2(*(const uint32_t*)(smc + OFF_XLO + off));
                float h0 = hh.x + hl.x, h1 = hh.y + hl.y;
                float2 bb = __half22float2(bh2[mi][nb][rb]);
                float2 wo = *(const float2*)(sWo + n);
                s += e0 + e1;
                d = fmaf(e0 * h0 * bb.x, wo.x, d);
                d = fmaf(e1 * h1 * bb.y, wo.y, d);
            }
            sv[mi * 2 + rb] = s; dv[mi * 2 + rb] = d;
        }
#pragma unroll
    for (int q = 0; q < 4; q++) {
        sv[q] += __shfl_xor_sync(FULL, sv[q], 1);
        sv[q] += __shfl_xor_sync(FULL, sv[q], 2);
        dv[q] += __shfl_xor_sync(FULL, dv[q], 1);
        dv[q] += __shfl_xor_sync(FULL, dv[q], 2);
    }
    if (tg == 0) {
#pragma unroll
        for (int q = 0; q < 4; q++) {
            int row = (q >> 1) * 16 + (q & 1) * 8 + gq;
            ps0[wid * 32 + row] = sv[q];
            ps1[wid * 32 + row] = dv[q];
        }
    }
    __syncthreads();
    if (tid < 32) {
        float S = 0.f, D = 0.f;
#pragma unroll
        for (int w = 0; w < 16; w++) { S += ps0[w * 32 + tid]; D += ps1[w * 32 + tid]; }
        float alpha = 0.f;
        const float4* sk4 = (const float4*)(sku + (size_t)(b0 + tid) * SKUD);
#pragma unroll
        for (int q = 0; q < 16; q++) {
            float4 s4 = sk4[q];
            alpha += s4.x * sWaWo[4 * q]     + s4.y * sWaWo[4 * q + 1]
                   + s4.z * sWaWo[4 * q + 2] + s4.w * sWaWo[4 * q + 3];
        }
        out[b0 + tid] = D / S + alpha;
    }
}

extern "C" void kernel_launch(void* const* d_in, const int* in_sizes, int n_in,
                              void* d_out, int out_size)
{
    const float* inputs   = (const float*)d_in[0];
    const float* sku      = (const float*)d_in[1];
    const float* deltas   = (const float*)d_in[2];
    const float* ln_gamma = (const float*)d_in[3];
    const float* ln_beta  = (const float*)d_in[4];
    const float* attn_w   = (const float*)d_in[5];
    const float* Wh       = (const float*)d_in[6];
    const float* Wah      = (const float*)d_in[7];
    const float* Waa      = (const float*)d_in[8];
    const float* Wb       = (const float*)d_in[9];
    const float* Wa       = (const float*)d_in[10];
    const float* Wo       = (const float*)d_in[11];
    float* out = (float*)d_out;

    int B = in_sizes[0] / H;
    prep_kernel<<<1088, 256>>>(Wah, Waa, Wb);
    cudaFuncSetAttribute(holiday_mma_kernel,
                         cudaFuncAttributeMaxDynamicSharedMemorySize, SMEM_BYTES);
    holiday_mma_kernel<<<B / ROWS, NTHR, SMEM_BYTES>>>(
        inputs, sku, deltas, ln_gamma, ln_beta, attn_w, Wh, Wa, Wo, out);
}